// round 4
// baseline (speedup 1.0000x reference)
#include <cuda_runtime.h>

#define NB   16
#define WIN  128
#define KF   256
#define EMB  256

typedef unsigned long long u64;

#define ADD2(d, a, b) asm("add.rn.f32x2 %0, %1, %2;" : "=l"(d) : "l"(a), "l"(b))
#define FMA2(d, a, b, c) asm("fma.rn.f32x2 %0, %1, %2, %3;" : "=l"(d) : "l"(a), "l"(b), "l"(c))
#define UNPK(lo, hi, v) asm("mov.b64 {%0, %1}, %2;" : "=f"(lo), "=f"(hi) : "l"(v))
#define PK(d, lo, hi) asm("mov.b64 %0, {%1, %2};" : "=l"(d) : "f"(lo), "f"(hi))

// ---------------- device scratch --------------------------------------------
__device__ float g_UI[NB * KF * EMB];        // hi + lin_b
__device__ float g_HJ[NB * KF * EMB];        // hj
__device__ float g_ATT[NB * KF * KF];        // exp(e - m_tile), per 64-j tile
__device__ float g_MS[NB * KF * 4 * 2];      // per (row, j-tile): max, sumexp

// ============================================================================
// gemmA: fused N=512 GEMM. rows = flat (b,k) 4096; cols e' in [0,512):
//   e'<256 -> UI[.., e'] (+lb);  e'>=256 -> HJ[.., e'-256]
// Block: 64 rows x 64 e', K=w=128 (f32x2-packed). 512 blocks, 3 CTAs/SM.
// ============================================================================
#define XP 144   // 144 % 32 = 16 -> 2-way write conflicts; u64-aligned rows
__global__ __launch_bounds__(256, 3)
void gemmA(const float* __restrict__ x, const float* __restrict__ lw,
           const float* __restrict__ lb)
{
    extern __shared__ float sm[];
    float* sXT = sm;                  // [64 rows][144] (w along row)
    float* sW  = sXT + 64 * XP;       // [64 e'][128 w]

    const int ktile = blockIdx.y;             // 0..63
    const int b  = ktile >> 2;
    const int k0 = (ktile & 3) * 64;
    const int ep = blockIdx.x * 64;           // e' base, 0..448
    const int side = (ep >= 256);             // 0 -> UI, 1 -> HJ
    const int eb   = ep & 255;                // emb base within side
    const int woff = side ? WIN : 0;
    const int t  = threadIdx.x;

    const float* xb = x + (size_t)b * WIN * KF + k0;
    for (int idx = t; idx < 128 * 64; idx += 256) {
        int w = idx >> 6, kk = idx & 63;
        sXT[kk * XP + w] = xb[w * KF + kk];
    }
    for (int idx = t; idx < 64 * 128; idx += 256) {
        int ee = idx >> 7, w = idx & 127;
        sW[idx] = lw[(eb + ee) * (2 * WIN) + woff + w];
    }
    __syncthreads();

    const int tk = t & 15;
    const int te = t >> 4;
    const u64* xp[4];  const u64* wp[4];
    #pragma unroll
    for (int ii = 0; ii < 4; ++ii) xp[ii] = (const u64*)(sXT + (tk + ii * 16) * XP);
    #pragma unroll
    for (int jj = 0; jj < 4; ++jj) wp[jj] = (const u64*)(sW + (te + jj * 16) * 128);

    u64 acc[4][4];
    #pragma unroll
    for (int ii = 0; ii < 4; ++ii)
        #pragma unroll
        for (int jj = 0; jj < 4; ++jj) acc[ii][jj] = 0ull;

    #pragma unroll 2
    for (int w = 0; w < 64; ++w) {
        u64 xv[4], av[4];
        #pragma unroll
        for (int ii = 0; ii < 4; ++ii) xv[ii] = xp[ii][w];
        #pragma unroll
        for (int jj = 0; jj < 4; ++jj) av[jj] = wp[jj][w];
        #pragma unroll
        for (int ii = 0; ii < 4; ++ii)
            #pragma unroll
            for (int jj = 0; jj < 4; ++jj)
                FMA2(acc[ii][jj], xv[ii], av[jj], acc[ii][jj]);
    }

    // staged, coalesced epilogue
    float* sO = sm;                  // 64x66 = 16.9KB, fits in sXT region
    __syncthreads();
    #pragma unroll
    for (int ii = 0; ii < 4; ++ii)
        #pragma unroll
        for (int jj = 0; jj < 4; ++jj) {
            float lo, hi; UNPK(lo, hi, acc[ii][jj]);
            float v = lo + hi;
            if (!side) v += lb[eb + te + jj * 16];
            sO[(tk + ii * 16) * 66 + te + jj * 16] = v;
        }
    __syncthreads();
    float* dst = (side ? g_HJ : g_UI) + ((size_t)b * KF + k0) * EMB + eb;
    for (int idx = t; idx < 64 * 64; idx += 256) {
        int r = idx >> 6, c = idx & 63;
        dst[(size_t)r * EMB + c] = sO[r * 66 + c];
    }
}

// ============================================================================
// kernB: e = AI+AJ + sum relu(UI+HJ)*0.8a + bias; store exp(e - m_tile) to
// g_ATT (coalesced via smem stage); (m_tile, sumexp) -> g_MS.
// i-tile 32, j-tile 64, 512 blocks.
// ============================================================================
#define BP 258
__global__ __launch_bounds__(256, 2)
void kernB(const float* __restrict__ a, const float* __restrict__ ab)
{
    extern __shared__ float sm[];
    float* sUI = sm;                   // [32][258]
    float* sHJ = sUI + 32 * BP;        // [64][258]
    float* sA8 = sHJ + 64 * BP;        // [256]
    float* sAI = sA8 + 256;            // [32]
    float* sAJ = sAI + 32;             // [64]

    const int b  = blockIdx.z;
    const int i0 = blockIdx.y * 32;
    const int jt = blockIdx.x;
    const int j0 = jt * 64;
    const int t  = threadIdx.x;

    const float4* gu = (const float4*)(g_UI + ((size_t)b * KF + i0) * EMB);
    for (int idx = t; idx < 32 * 64; idx += 256) {
        int r = idx >> 6, c = idx & 63;
        float4 v = gu[r * 64 + c];
        float2* d = (float2*)(sUI + r * BP + c * 4);
        d[0] = make_float2(v.x, v.y); d[1] = make_float2(v.z, v.w);
    }
    const float4* gh = (const float4*)(g_HJ + ((size_t)b * KF + j0) * EMB);
    for (int idx = t; idx < 64 * 64; idx += 256) {
        int r = idx >> 6, c = idx & 63;
        float4 v = gh[r * 64 + c];
        float2* d = (float2*)(sHJ + r * BP + c * 4);
        d[0] = make_float2(v.x, v.y); d[1] = make_float2(v.z, v.w);
    }
    sA8[t] = 0.8f * a[t];
    __syncthreads();

    // in-block row dots: AI = 0.25*dot(UI, 0.8a), AJ likewise
    {
        const int warp = t >> 5, lane = t & 31;
        #pragma unroll
        for (int rr = 0; rr < 4; ++rr) {
            int r = warp * 4 + rr;
            float s = 0.f;
            #pragma unroll
            for (int q = 0; q < 8; ++q) s += sUI[r * BP + lane + q * 32] * sA8[lane + q * 32];
            #pragma unroll
            for (int off = 16; off; off >>= 1) s += __shfl_xor_sync(0xffffffffu, s, off);
            if (lane == 0) sAI[r] = 0.25f * s;
        }
        #pragma unroll
        for (int rr = 0; rr < 8; ++rr) {
            int r = warp * 8 + rr;
            float s = 0.f;
            #pragma unroll
            for (int q = 0; q < 8; ++q) s += sHJ[r * BP + lane + q * 32] * sA8[lane + q * 32];
            #pragma unroll
            for (int off = 16; off; off >>= 1) s += __shfl_xor_sync(0xffffffffu, s, off);
            if (lane == 0) sAJ[r] = 0.25f * s;
        }
    }
    __syncthreads();

    const int ti = t >> 4;
    const int jl = t & 15;
    const u64* u0p = (const u64*)(sUI + ti * BP);
    const u64* u1p = (const u64*)(sUI + (ti + 16) * BP);
    const u64* vp[4];
    #pragma unroll
    for (int q = 0; q < 4; ++q) vp[q] = (const u64*)(sHJ + (jl + q * 16) * BP);
    const u64* ap = (const u64*)sA8;

    u64 acc0[4], acc1[4];
    #pragma unroll
    for (int q = 0; q < 4; ++q) { acc0[q] = 0ull; acc1[q] = 0ull; }

    #pragma unroll 2
    for (int e = 0; e < 128; ++e) {
        u64 ae = ap[e], u0 = u0p[e], u1 = u1p[e];
        #pragma unroll
        for (int q = 0; q < 4; ++q) {
            u64 v = vp[q][e];
            u64 s0, s1;
            ADD2(s0, u0, v); ADD2(s1, u1, v);
            float x0, y0, x1, y1;
            UNPK(x0, y0, s0); UNPK(x1, y1, s1);
            x0 = fmaxf(x0, 0.f); y0 = fmaxf(y0, 0.f);
            x1 = fmaxf(x1, 0.f); y1 = fmaxf(y1, 0.f);
            u64 r0, r1; PK(r0, x0, y0); PK(r1, x1, y1);
            FMA2(acc0[q], r0, ae, acc0[q]);
            FMA2(acc1[q], r1, ae, acc1[q]);
        }
    }

    // epilogue: final e values, tile softmax partials, exp, staged store
    const float ai0 = sAI[ti], ai1 = sAI[ti + 16];
    float v0[4], v1[4];
    #pragma unroll
    for (int q = 0; q < 4; ++q) {
        int jc = jl + q * 16;
        int j  = j0 + jc;
        float lo, hi;
        UNPK(lo, hi, acc0[q]);
        v0[q] = lo + hi + ai0 + sAJ[jc] + ab[(size_t)(i0 + ti) * KF + j];
        UNPK(lo, hi, acc1[q]);
        v1[q] = lo + hi + ai1 + sAJ[jc] + ab[(size_t)(i0 + ti + 16) * KF + j];
    }
    float m0 = fmaxf(fmaxf(v0[0], v0[1]), fmaxf(v0[2], v0[3]));
    float m1 = fmaxf(fmaxf(v1[0], v1[1]), fmaxf(v1[2], v1[3]));
    #pragma unroll
    for (int off = 8; off; off >>= 1) {
        m0 = fmaxf(m0, __shfl_xor_sync(0xffffffffu, m0, off));
        m1 = fmaxf(m1, __shfl_xor_sync(0xffffffffu, m1, off));
    }
    float e0[4], e1[4];
    float s0 = 0.f, s1 = 0.f;
    #pragma unroll
    for (int q = 0; q < 4; ++q) {
        e0[q] = __expf(v0[q] - m0); s0 += e0[q];
        e1[q] = __expf(v1[q] - m1); s1 += e1[q];
    }
    #pragma unroll
    for (int off = 8; off; off >>= 1) {
        s0 += __shfl_xor_sync(0xffffffffu, s0, off);
        s1 += __shfl_xor_sync(0xffffffffu, s1, off);
    }
    if (jl == 0) {
        size_t r0i = (size_t)(b * KF + i0 + ti) * 8 + jt * 2;
        size_t r1i = (size_t)(b * KF + i0 + ti + 16) * 8 + jt * 2;
        g_MS[r0i] = m0; g_MS[r0i + 1] = s0;
        g_MS[r1i] = m1; g_MS[r1i + 1] = s1;
    }

    // stage exps (32 x 64) in smem, then coalesced store
    float* sE = sm;                  // reuse sUI region (32*66 < 32*258)
    __syncthreads();
    #pragma unroll
    for (int q = 0; q < 4; ++q) {
        int jc = jl + q * 16;
        sE[ti * 66 + jc]        = e0[q];
        sE[(ti + 16) * 66 + jc] = e1[q];
    }
    __syncthreads();
    for (int idx = t; idx < 32 * 64; idx += 256) {
        int r = idx >> 6, c = idx & 63;
        g_ATT[((size_t)b * KF + i0 + r) * KF + j0 + c] = sE[r * 66 + c];
    }
}

// ============================================================================
// kernC: out[b,w,i] = sigmoid( sum_jt corr[i,jt] * sum_j att'[i,j]*x[w,j] )
// corr = exp(m_t - M) / S_total. Staged, coalesced output.
// ============================================================================
#define CP 66
__global__ __launch_bounds__(256)
void kernC(const float* __restrict__ x, float* __restrict__ out)
{
    __shared__ float sAtt[64 * CP];
    __shared__ float sX[32 * CP];
    __shared__ float sOut[32 * CP];
    __shared__ float sCorr[64 * 4];

    const int b  = blockIdx.z;
    const int w0 = blockIdx.y * 32;
    const int i0 = blockIdx.x * 64;
    const int t  = threadIdx.x;
    const int il = t & 15;
    const int tw = t >> 4;

    if (t < 64) {
        const float* p = g_MS + (size_t)(b * KF + i0 + t) * 8;
        float m[4], s[4];
        #pragma unroll
        for (int q = 0; q < 4; ++q) { m[q] = p[q * 2]; s[q] = p[q * 2 + 1]; }
        float M = fmaxf(fmaxf(m[0], m[1]), fmaxf(m[2], m[3]));
        float ex[4];
        float S = 0.f;
        #pragma unroll
        for (int q = 0; q < 4; ++q) { ex[q] = __expf(m[q] - M); S += s[q] * ex[q]; }
        float inv = 1.0f / S;
        #pragma unroll
        for (int q = 0; q < 4; ++q) sCorr[t * 4 + q] = ex[q] * inv;
    }

    u64 acc[4][2];
    #pragma unroll
    for (int qi = 0; qi < 4; ++qi) { acc[qi][0] = 0ull; acc[qi][1] = 0ull; }

    for (int jt = 0; jt < 4; ++jt) {
        __syncthreads();
        const int j0 = jt * 64;
        for (int idx = t; idx < 64 * 16; idx += 256) {
            int r = idx >> 4, c = idx & 15;
            float4 v = *(const float4*)(g_ATT + ((size_t)b * KF + i0 + r) * KF + j0 + c * 4);
            float2* d = (float2*)(sAtt + r * CP + c * 4);
            d[0] = make_float2(v.x, v.y); d[1] = make_float2(v.z, v.w);
        }
        for (int idx = t; idx < 32 * 16; idx += 256) {
            int r = idx >> 4, c = idx & 15;
            float4 v = *(const float4*)(x + ((size_t)b * WIN + w0 + r) * KF + j0 + c * 4);
            float2* d = (float2*)(sX + r * CP + c * 4);
            d[0] = make_float2(v.x, v.y); d[1] = make_float2(v.z, v.w);
        }
        __syncthreads();

        const u64* xp0 = (const u64*)(sX + tw * CP);
        const u64* xp1 = (const u64*)(sX + (tw + 16) * CP);
        const u64* avp[4];
        #pragma unroll
        for (int qi = 0; qi < 4; ++qi) avp[qi] = (const u64*)(sAtt + (il + qi * 16) * CP);

        u64 accP[4][2];
        #pragma unroll
        for (int qi = 0; qi < 4; ++qi) { accP[qi][0] = 0ull; accP[qi][1] = 0ull; }

        #pragma unroll 4
        for (int j = 0; j < 32; ++j) {
            u64 x0 = xp0[j], x1 = xp1[j];
            #pragma unroll
            for (int qi = 0; qi < 4; ++qi) {
                u64 av = avp[qi][j];
                FMA2(accP[qi][0], av, x0, accP[qi][0]);
                FMA2(accP[qi][1], av, x1, accP[qi][1]);
            }
        }
        #pragma unroll
        for (int qi = 0; qi < 4; ++qi) {
            float c = sCorr[(il + qi * 16) * 4 + jt];
            u64 c2; PK(c2, c, c);
            FMA2(acc[qi][0], accP[qi][0], c2, acc[qi][0]);
            FMA2(acc[qi][1], accP[qi][1], c2, acc[qi][1]);
        }
    }

    __syncthreads();
    #pragma unroll
    for (int qi = 0; qi < 4; ++qi) {
        #pragma unroll
        for (int qw = 0; qw < 2; ++qw) {
            float lo, hi; UNPK(lo, hi, acc[qi][qw]);
            float s = lo + hi;
            sOut[(tw + qw * 16) * CP + il + qi * 16] = 1.0f / (1.0f + __expf(-s));
        }
    }
    __syncthreads();
    for (int idx = t; idx < 32 * 64; idx += 256) {
        int r = idx >> 6, c = idx & 63;
        out[((size_t)b * WIN + w0 + r) * KF + i0 + c] = sOut[r * CP + c];
    }
}

// ============================================================================
extern "C" void kernel_launch(void* const* d_in, const int* in_sizes, int n_in,
                              void* d_out, int out_size)
{
    const float* x   = (const float*)d_in[0];
    const float* lw  = (const float*)d_in[1];
    const float* lb  = (const float*)d_in[2];
    const float* a   = (const float*)d_in[3];
    const float* ab  = (const float*)d_in[4];
    float* out = (float*)d_out;

    const int smemA = (64 * XP + 64 * 128) * 4;                      // ~68 KB
    const int smemB = (32 * BP + 64 * BP + 256 + 32 + 64) * 4;       // ~98 KB

    cudaFuncSetAttribute(gemmA, cudaFuncAttributeMaxDynamicSharedMemorySize, smemA);
    cudaFuncSetAttribute(kernB, cudaFuncAttributeMaxDynamicSharedMemorySize, smemB);

    gemmA<<<dim3(8, 64), 256, smemA>>>(x, lw, lb);
    kernB<<<dim3(4, 8, NB), 256, smemB>>>(a, ab);
    kernC<<<dim3(4, 4, NB), 256>>>(x, out);
}

// round 5
// speedup vs baseline: 1.2919x; 1.2919x over previous
#include <cuda_runtime.h>

#define NB   16
#define WIN  128
#define KF   256
#define EMB  256

typedef unsigned long long u64;

#define ADD2(d, a, b) asm("add.rn.f32x2 %0, %1, %2;" : "=l"(d) : "l"(a), "l"(b))
#define FMA2(d, a, b, c) asm("fma.rn.f32x2 %0, %1, %2, %3;" : "=l"(d) : "l"(a), "l"(b), "l"(c))
#define UNPK(lo, hi, v) asm("mov.b64 {%0, %1}, %2;" : "=f"(lo), "=f"(hi) : "l"(v))
#define PK(d, lo, hi) asm("mov.b64 %0, {%1, %2};" : "=l"(d) : "f"(lo), "f"(hi))

// ---------------- device scratch --------------------------------------------
__device__ float g_UI[NB * KF * EMB];        // hi + lin_b
__device__ float g_HJ[NB * KF * EMB];        // hj
__device__ float g_ATT[NB * KF * KF];        // exp(e - m_tile), per 64-j tile
__device__ float g_MS[NB * KF * 4 * 2];      // per (row, j-tile): max, sumexp

// ============================================================================
// gemmA: fused N=512 GEMM. rows = flat (b,k); cols e' in [0,512):
//   e'<256 -> UI (+lb);  e'>=256 -> HJ.
// Block: 128 threads, tile 64 rows x 128 e', K=w=128 packed as 64 u64.
// Thread micro-tile 8x8 (balanced: LDS bytes == fma capacity). Pitch 130.
// Grid 256 blocks, 2 CTAs/SM -> single wave.
// ============================================================================
#define XP 130   // 130 % 32 = 2 -> conflict-free row reads
__global__ __launch_bounds__(128)
void gemmA(const float* __restrict__ x, const float* __restrict__ lw,
           const float* __restrict__ lb)
{
    extern __shared__ float sm[];
    float* sXT = sm;                  // [64 k][130]  (w along row)
    float* sW  = sXT + 64 * XP;       // [128 e'][130]

    const int ktile = blockIdx.y;             // 0..63
    const int b  = ktile >> 2;
    const int k0 = (ktile & 3) * 64;
    const int ep = blockIdx.x * 128;          // e' base: 0,128,256,384
    const int side = (ep >= 256);             // 0 -> UI, 1 -> HJ
    const int eb   = ep & 255;
    const int woff = side ? WIN : 0;
    const int t  = threadIdx.x;

    const float* xb = x + (size_t)b * WIN * KF + k0;
    for (int idx = t; idx < 128 * 64; idx += 128) {
        int w = idx >> 6, kk = idx & 63;
        sXT[kk * XP + w] = xb[w * KF + kk];
    }
    for (int idx = t; idx < 128 * 128; idx += 128) {
        int ee = idx >> 7, w = idx & 127;
        sW[ee * XP + w] = lw[(eb + ee) * (2 * WIN) + woff + w];
    }
    __syncthreads();

    const int tk = t & 7;    // k rows: tk + ii*8   (ii<8)
    const int te = t >> 3;   // e' cols: te + jj*16 (jj<8)
    const u64* xp[8];  const u64* wp[8];
    #pragma unroll
    for (int ii = 0; ii < 8; ++ii) xp[ii] = (const u64*)(sXT + (tk + ii * 8) * XP);
    #pragma unroll
    for (int jj = 0; jj < 8; ++jj) wp[jj] = (const u64*)(sW + (te + jj * 16) * XP);

    u64 acc[8][8];
    #pragma unroll
    for (int ii = 0; ii < 8; ++ii)
        #pragma unroll
        for (int jj = 0; jj < 8; ++jj) acc[ii][jj] = 0ull;

    for (int w = 0; w < 64; ++w) {
        u64 xv[8], wv[8];
        #pragma unroll
        for (int ii = 0; ii < 8; ++ii) xv[ii] = xp[ii][w];
        #pragma unroll
        for (int jj = 0; jj < 8; ++jj) wv[jj] = wp[jj][w];
        #pragma unroll
        for (int ii = 0; ii < 8; ++ii)
            #pragma unroll
            for (int jj = 0; jj < 8; ++jj)
                FMA2(acc[ii][jj], xv[ii], wv[jj], acc[ii][jj]);
    }

    // bias (UI side only), reduce pairs, stage, coalesced store
    float lbv[8];
    if (!side) {
        #pragma unroll
        for (int jj = 0; jj < 8; ++jj) lbv[jj] = __ldg(lb + eb + te + jj * 16);
    } else {
        #pragma unroll
        for (int jj = 0; jj < 8; ++jj) lbv[jj] = 0.f;
    }

    float* sO = sm;                  // 64 x 130 region (reuse sXT)
    __syncthreads();
    #pragma unroll
    for (int ii = 0; ii < 8; ++ii)
        #pragma unroll
        for (int jj = 0; jj < 8; ++jj) {
            float lo, hi; UNPK(lo, hi, acc[ii][jj]);
            sO[(tk + ii * 8) * XP + te + jj * 16] = lo + hi + lbv[jj];
        }
    __syncthreads();
    float* dst = (side ? g_HJ : g_UI) + ((size_t)b * KF + k0) * EMB + eb;
    for (int idx = t; idx < 64 * 64; idx += 128) {
        int r = idx >> 6, c2 = idx & 63;
        *(float2*)(dst + (size_t)r * EMB + c2 * 2) = *(float2*)(sO + r * XP + c2 * 2);
    }
}

// ============================================================================
// kernB: e = AI+AJ + sum relu(UI+HJ)*0.8a + bias; store exp(e - m_tile) to
// g_ATT (coalesced via smem stage); (m_tile, sumexp) -> g_MS.
// i-tile 32, j-tile 64, 512 blocks.
// ============================================================================
#define BP 258
__global__ __launch_bounds__(256, 2)
void kernB(const float* __restrict__ a, const float* __restrict__ ab)
{
    extern __shared__ float sm[];
    float* sUI = sm;                   // [32][258]
    float* sHJ = sUI + 32 * BP;        // [64][258]
    float* sA8 = sHJ + 64 * BP;        // [256]
    float* sAI = sA8 + 256;            // [32]
    float* sAJ = sAI + 32;             // [64]

    const int b  = blockIdx.z;
    const int i0 = blockIdx.y * 32;
    const int jt = blockIdx.x;
    const int j0 = jt * 64;
    const int t  = threadIdx.x;

    const float4* gu = (const float4*)(g_UI + ((size_t)b * KF + i0) * EMB);
    for (int idx = t; idx < 32 * 64; idx += 256) {
        int r = idx >> 6, c = idx & 63;
        float4 v = gu[r * 64 + c];
        float2* d = (float2*)(sUI + r * BP + c * 4);
        d[0] = make_float2(v.x, v.y); d[1] = make_float2(v.z, v.w);
    }
    const float4* gh = (const float4*)(g_HJ + ((size_t)b * KF + j0) * EMB);
    for (int idx = t; idx < 64 * 64; idx += 256) {
        int r = idx >> 6, c = idx & 63;
        float4 v = gh[r * 64 + c];
        float2* d = (float2*)(sHJ + r * BP + c * 4);
        d[0] = make_float2(v.x, v.y); d[1] = make_float2(v.z, v.w);
    }
    sA8[t] = 0.8f * a[t];
    __syncthreads();

    // in-block row dots: AI = 0.25*dot(UI, 0.8a), AJ likewise
    {
        const int warp = t >> 5, lane = t & 31;
        #pragma unroll
        for (int rr = 0; rr < 4; ++rr) {
            int r = warp * 4 + rr;
            float s = 0.f;
            #pragma unroll
            for (int q = 0; q < 8; ++q) s += sUI[r * BP + lane + q * 32] * sA8[lane + q * 32];
            #pragma unroll
            for (int off = 16; off; off >>= 1) s += __shfl_xor_sync(0xffffffffu, s, off);
            if (lane == 0) sAI[r] = 0.25f * s;
        }
        #pragma unroll
        for (int rr = 0; rr < 8; ++rr) {
            int r = warp * 8 + rr;
            float s = 0.f;
            #pragma unroll
            for (int q = 0; q < 8; ++q) s += sHJ[r * BP + lane + q * 32] * sA8[lane + q * 32];
            #pragma unroll
            for (int off = 16; off; off >>= 1) s += __shfl_xor_sync(0xffffffffu, s, off);
            if (lane == 0) sAJ[r] = 0.25f * s;
        }
    }
    __syncthreads();

    const int ti = t >> 4;
    const int jl = t & 15;
    const u64* u0p = (const u64*)(sUI + ti * BP);
    const u64* u1p = (const u64*)(sUI + (ti + 16) * BP);
    const u64* vp[4];
    #pragma unroll
    for (int q = 0; q < 4; ++q) vp[q] = (const u64*)(sHJ + (jl + q * 16) * BP);
    const u64* ap = (const u64*)sA8;

    u64 acc0[4], acc1[4];
    #pragma unroll
    for (int q = 0; q < 4; ++q) { acc0[q] = 0ull; acc1[q] = 0ull; }

    #pragma unroll 2
    for (int e = 0; e < 128; ++e) {
        u64 ae = ap[e], u0 = u0p[e], u1 = u1p[e];
        #pragma unroll
        for (int q = 0; q < 4; ++q) {
            u64 v = vp[q][e];
            u64 s0, s1;
            ADD2(s0, u0, v); ADD2(s1, u1, v);
            float x0, y0, x1, y1;
            UNPK(x0, y0, s0); UNPK(x1, y1, s1);
            x0 = fmaxf(x0, 0.f); y0 = fmaxf(y0, 0.f);
            x1 = fmaxf(x1, 0.f); y1 = fmaxf(y1, 0.f);
            u64 r0, r1; PK(r0, x0, y0); PK(r1, x1, y1);
            FMA2(acc0[q], r0, ae, acc0[q]);
            FMA2(acc1[q], r1, ae, acc1[q]);
        }
    }

    // epilogue: final e values, tile softmax partials, exp, staged store
    const float ai0 = sAI[ti], ai1 = sAI[ti + 16];
    float v0[4], v1[4];
    #pragma unroll
    for (int q = 0; q < 4; ++q) {
        int jc = jl + q * 16;
        int j  = j0 + jc;
        float lo, hi;
        UNPK(lo, hi, acc0[q]);
        v0[q] = lo + hi + ai0 + sAJ[jc] + ab[(size_t)(i0 + ti) * KF + j];
        UNPK(lo, hi, acc1[q]);
        v1[q] = lo + hi + ai1 + sAJ[jc] + ab[(size_t)(i0 + ti + 16) * KF + j];
    }
    float m0 = fmaxf(fmaxf(v0[0], v0[1]), fmaxf(v0[2], v0[3]));
    float m1 = fmaxf(fmaxf(v1[0], v1[1]), fmaxf(v1[2], v1[3]));
    #pragma unroll
    for (int off = 8; off; off >>= 1) {
        m0 = fmaxf(m0, __shfl_xor_sync(0xffffffffu, m0, off));
        m1 = fmaxf(m1, __shfl_xor_sync(0xffffffffu, m1, off));
    }
    float e0[4], e1[4];
    float s0 = 0.f, s1 = 0.f;
    #pragma unroll
    for (int q = 0; q < 4; ++q) {
        e0[q] = __expf(v0[q] - m0); s0 += e0[q];
        e1[q] = __expf(v1[q] - m1); s1 += e1[q];
    }
    #pragma unroll
    for (int off = 8; off; off >>= 1) {
        s0 += __shfl_xor_sync(0xffffffffu, s0, off);
        s1 += __shfl_xor_sync(0xffffffffu, s1, off);
    }
    if (jl == 0) {
        size_t r0i = (size_t)(b * KF + i0 + ti) * 8 + jt * 2;
        size_t r1i = (size_t)(b * KF + i0 + ti + 16) * 8 + jt * 2;
        g_MS[r0i] = m0; g_MS[r0i + 1] = s0;
        g_MS[r1i] = m1; g_MS[r1i + 1] = s1;
    }

    float* sE = sm;                  // reuse sUI region
    __syncthreads();
    #pragma unroll
    for (int q = 0; q < 4; ++q) {
        int jc = jl + q * 16;
        sE[ti * 66 + jc]        = e0[q];
        sE[(ti + 16) * 66 + jc] = e1[q];
    }
    __syncthreads();
    for (int idx = t; idx < 32 * 64; idx += 256) {
        int r = idx >> 6, c = idx & 63;
        g_ATT[((size_t)b * KF + i0 + r) * KF + j0 + c] = sE[r * 66 + c];
    }
}

// ============================================================================
// kernC: out[b,w,i] = sigmoid( sum_jt corr[i,jt] * sum_j att'[i,j]*x[w,j] )
// corr = exp(m_t - M) / S_total. Staged, coalesced output.
// ============================================================================
#define CP 66
__global__ __launch_bounds__(256)
void kernC(const float* __restrict__ x, float* __restrict__ out)
{
    __shared__ float sAtt[64 * CP];
    __shared__ float sX[32 * CP];
    __shared__ float sOut[32 * CP];
    __shared__ float sCorr[64 * 4];

    const int b  = blockIdx.z;
    const int w0 = blockIdx.y * 32;
    const int i0 = blockIdx.x * 64;
    const int t  = threadIdx.x;
    const int il = t & 15;
    const int tw = t >> 4;

    if (t < 64) {
        const float* p = g_MS + (size_t)(b * KF + i0 + t) * 8;
        float m[4], s[4];
        #pragma unroll
        for (int q = 0; q < 4; ++q) { m[q] = p[q * 2]; s[q] = p[q * 2 + 1]; }
        float M = fmaxf(fmaxf(m[0], m[1]), fmaxf(m[2], m[3]));
        float ex[4];
        float S = 0.f;
        #pragma unroll
        for (int q = 0; q < 4; ++q) { ex[q] = __expf(m[q] - M); S += s[q] * ex[q]; }
        float inv = 1.0f / S;
        #pragma unroll
        for (int q = 0; q < 4; ++q) sCorr[t * 4 + q] = ex[q] * inv;
    }

    u64 acc[4][2];
    #pragma unroll
    for (int qi = 0; qi < 4; ++qi) { acc[qi][0] = 0ull; acc[qi][1] = 0ull; }

    for (int jt = 0; jt < 4; ++jt) {
        __syncthreads();
        const int j0 = jt * 64;
        for (int idx = t; idx < 64 * 16; idx += 256) {
            int r = idx >> 4, c = idx & 15;
            float4 v = *(const float4*)(g_ATT + ((size_t)b * KF + i0 + r) * KF + j0 + c * 4);
            float2* d = (float2*)(sAtt + r * CP + c * 4);
            d[0] = make_float2(v.x, v.y); d[1] = make_float2(v.z, v.w);
        }
        for (int idx = t; idx < 32 * 16; idx += 256) {
            int r = idx >> 4, c = idx & 15;
            float4 v = *(const float4*)(x + ((size_t)b * WIN + w0 + r) * KF + j0 + c * 4);
            float2* d = (float2*)(sX + r * CP + c * 4);
            d[0] = make_float2(v.x, v.y); d[1] = make_float2(v.z, v.w);
        }
        __syncthreads();

        const u64* xp0 = (const u64*)(sX + tw * CP);
        const u64* xp1 = (const u64*)(sX + (tw + 16) * CP);
        const u64* avp[4];
        #pragma unroll
        for (int qi = 0; qi < 4; ++qi) avp[qi] = (const u64*)(sAtt + (il + qi * 16) * CP);

        u64 accP[4][2];
        #pragma unroll
        for (int qi = 0; qi < 4; ++qi) { accP[qi][0] = 0ull; accP[qi][1] = 0ull; }

        #pragma unroll 4
        for (int j = 0; j < 32; ++j) {
            u64 x0 = xp0[j], x1 = xp1[j];
            #pragma unroll
            for (int qi = 0; qi < 4; ++qi) {
                u64 av = avp[qi][j];
                FMA2(accP[qi][0], av, x0, accP[qi][0]);
                FMA2(accP[qi][1], av, x1, accP[qi][1]);
            }
        }
        #pragma unroll
        for (int qi = 0; qi < 4; ++qi) {
            float c = sCorr[(il + qi * 16) * 4 + jt];
            u64 c2; PK(c2, c, c);
            FMA2(acc[qi][0], accP[qi][0], c2, acc[qi][0]);
            FMA2(acc[qi][1], accP[qi][1], c2, acc[qi][1]);
        }
    }

    __syncthreads();
    #pragma unroll
    for (int qi = 0; qi < 4; ++qi) {
        #pragma unroll
        for (int qw = 0; qw < 2; ++qw) {
            float lo, hi; UNPK(lo, hi, acc[qi][qw]);
            float s = lo + hi;
            sOut[(tw + qw * 16) * CP + il + qi * 16] = 1.0f / (1.0f + __expf(-s));
        }
    }
    __syncthreads();
    for (int idx = t; idx < 32 * 64; idx += 256) {
        int r = idx >> 6, c = idx & 63;
        out[((size_t)b * WIN + w0 + r) * KF + i0 + c] = sOut[r * CP + c];
    }
}

// ============================================================================
extern "C" void kernel_launch(void* const* d_in, const int* in_sizes, int n_in,
                              void* d_out, int out_size)
{
    const float* x   = (const float*)d_in[0];
    const float* lw  = (const float*)d_in[1];
    const float* lb  = (const float*)d_in[2];
    const float* a   = (const float*)d_in[3];
    const float* ab  = (const float*)d_in[4];
    float* out = (float*)d_out;

    const int smemA = (64 * XP + 128 * XP) * 4;                      // ~97.5 KB
    const int smemB = (32 * BP + 64 * BP + 256 + 32 + 64) * 4;       // ~98 KB

    cudaFuncSetAttribute(gemmA, cudaFuncAttributeMaxDynamicSharedMemorySize, smemA);
    cudaFuncSetAttribute(kernB, cudaFuncAttributeMaxDynamicSharedMemorySize, smemB);

    gemmA<<<dim3(4, 64), 128, smemA>>>(x, lw, lb);
    kernB<<<dim3(4, 8, NB), 256, smemB>>>(a, ab);
    kernC<<<dim3(4, 4, NB), 256>>>(x, out);
}

// round 6
// speedup vs baseline: 1.3656x; 1.0570x over previous
#include <cuda_runtime.h>

#define NB   16
#define WIN  128
#define KF   256
#define EMB  256

typedef unsigned long long u64;

#define ADD2(d, a, b) asm("add.rn.f32x2 %0, %1, %2;" : "=l"(d) : "l"(a), "l"(b))
#define FMA2(d, a, b, c) asm("fma.rn.f32x2 %0, %1, %2, %3;" : "=l"(d) : "l"(a), "l"(b), "l"(c))
#define UNPK(lo, hi, v) asm("mov.b64 {%0, %1}, %2;" : "=f"(lo), "=f"(hi) : "l"(v))
#define PK(d, lo, hi) asm("mov.b64 %0, {%1, %2};" : "=l"(d) : "f"(lo), "f"(hi))

#define ABSMASK 0x7FFFFFFF7FFFFFFFull

// ---------------- device scratch --------------------------------------------
__device__ float g_UI[NB * KF * EMB];        // hi + lin_b
__device__ float g_HJ[NB * KF * EMB];        // hj
__device__ float g_ATT[NB * KF * KF];        // exp(e - m_tile), per 64-j tile
__device__ float g_MS[NB * KF * 4 * 2];      // per (row, j-tile): max, sumexp

// ============================================================================
// gemmA: fused N=512 GEMM. rows = flat (b,k); cols e' in [0,512):
//   e'<256 -> UI (+lb);  e'>=256 -> HJ.
// 256 threads, tile 64 rows x 128 e', K=w=128 (64 u64 pairs), micro 4x8.
// Pitch 130 (conflict-free). 2 CTAs/SM -> 16 warps/SM. Grid 256 = 1 wave.
// ============================================================================
#define XP 130
__global__ __launch_bounds__(256, 2)
void gemmA(const float* __restrict__ x, const float* __restrict__ lw,
           const float* __restrict__ lb)
{
    extern __shared__ float sm[];
    float* sXT = sm;                  // [64 k][130]  (w along row)
    float* sW  = sXT + 64 * XP;       // [128 e'][130]

    const int ktile = blockIdx.y;             // 0..63
    const int b  = ktile >> 2;
    const int k0 = (ktile & 3) * 64;
    const int ep = blockIdx.x * 128;          // 0,128,256,384
    const int side = (ep >= 256);             // 0 -> UI, 1 -> HJ
    const int eb   = ep & 255;
    const int woff = side ? WIN : 0;
    const int t  = threadIdx.x;

    const float* xb = x + (size_t)b * WIN * KF + k0;
    for (int idx = t; idx < 128 * 64; idx += 256) {
        int w = idx >> 6, kk = idx & 63;
        sXT[kk * XP + w] = xb[w * KF + kk];
    }
    for (int idx = t; idx < 128 * 128; idx += 256) {
        int ee = idx >> 7, w = idx & 127;
        sW[ee * XP + w] = lw[(eb + ee) * (2 * WIN) + woff + w];
    }
    __syncthreads();

    const int tk = t & 15;   // k rows: tk + ii*16  (ii<4)
    const int te = t >> 4;   // e' cols: te + jj*16 (jj<8)
    const u64* xp[4];  const u64* wp[8];
    #pragma unroll
    for (int ii = 0; ii < 4; ++ii) xp[ii] = (const u64*)(sXT + (tk + ii * 16) * XP);
    #pragma unroll
    for (int jj = 0; jj < 8; ++jj) wp[jj] = (const u64*)(sW + (te + jj * 16) * XP);

    u64 acc[4][8];
    #pragma unroll
    for (int ii = 0; ii < 4; ++ii)
        #pragma unroll
        for (int jj = 0; jj < 8; ++jj) acc[ii][jj] = 0ull;

    for (int w = 0; w < 64; ++w) {
        u64 xv[4], wv[8];
        #pragma unroll
        for (int ii = 0; ii < 4; ++ii) xv[ii] = xp[ii][w];
        #pragma unroll
        for (int jj = 0; jj < 8; ++jj) wv[jj] = wp[jj][w];
        #pragma unroll
        for (int ii = 0; ii < 4; ++ii)
            #pragma unroll
            for (int jj = 0; jj < 8; ++jj)
                FMA2(acc[ii][jj], xv[ii], wv[jj], acc[ii][jj]);
    }

    float lbv[8];
    #pragma unroll
    for (int jj = 0; jj < 8; ++jj)
        lbv[jj] = side ? 0.f : __ldg(lb + eb + te + jj * 16);

    float* sO = sm;                  // reuse sXT region: [64][130]
    __syncthreads();
    #pragma unroll
    for (int ii = 0; ii < 4; ++ii)
        #pragma unroll
        for (int jj = 0; jj < 8; ++jj) {
            float lo, hi; UNPK(lo, hi, acc[ii][jj]);
            sO[(tk + ii * 16) * XP + te + jj * 16] = lo + hi + lbv[jj];
        }
    __syncthreads();
    float* dst = (side ? g_HJ : g_UI) + ((size_t)b * KF + k0) * EMB + eb;
    for (int idx = t; idx < 64 * 64; idx += 256) {
        int r = idx >> 6, c = idx & 63;
        *(float2*)(dst + (size_t)r * EMB + c * 2) = *(float2*)(sO + r * XP + c * 2);
    }
}

// ============================================================================
// kernB: e = 0.6(dot_i+dot_j) + sum 0.4a|u+v| + bias; store exp(e - m_tile)
// to g_ATT; (m_tile, sumexp) -> g_MS.  leaky(s)=0.6s+0.4|s| identity:
// linear part separable into row dots, abs part = packed AND mask (no
// pack/unpack movs in the hot loop). i-tile 32, j-tile 64, 512 blocks.
// ============================================================================
#define BP 258
__global__ __launch_bounds__(256, 2)
void kernB(const float* __restrict__ a, const float* __restrict__ ab)
{
    extern __shared__ float sm[];
    float* sUI = sm;                   // [32][258]
    float* sHJ = sUI + 32 * BP;        // [64][258]
    float* sA4 = sHJ + 64 * BP;        // [256]  0.4*a
    float* sAI = sA4 + 256;            // [32]
    float* sAJ = sAI + 32;             // [64]

    const int b  = blockIdx.z;
    const int i0 = blockIdx.y * 32;
    const int jt = blockIdx.x;
    const int j0 = jt * 64;
    const int t  = threadIdx.x;

    const float4* gu = (const float4*)(g_UI + ((size_t)b * KF + i0) * EMB);
    for (int idx = t; idx < 32 * 64; idx += 256) {
        int r = idx >> 6, c = idx & 63;
        float4 v = gu[r * 64 + c];
        float2* d = (float2*)(sUI + r * BP + c * 4);
        d[0] = make_float2(v.x, v.y); d[1] = make_float2(v.z, v.w);
    }
    const float4* gh = (const float4*)(g_HJ + ((size_t)b * KF + j0) * EMB);
    for (int idx = t; idx < 64 * 64; idx += 256) {
        int r = idx >> 6, c = idx & 63;
        float4 v = gh[r * 64 + c];
        float2* d = (float2*)(sHJ + r * BP + c * 4);
        d[0] = make_float2(v.x, v.y); d[1] = make_float2(v.z, v.w);
    }
    sA4[t] = 0.4f * a[t];
    __syncthreads();

    // row dots: 0.6*dot(row, a) = 1.5*dot(row, 0.4a)
    {
        const int warp = t >> 5, lane = t & 31;
        #pragma unroll
        for (int rr = 0; rr < 4; ++rr) {
            int r = warp * 4 + rr;
            float s = 0.f;
            #pragma unroll
            for (int q = 0; q < 8; ++q) s += sUI[r * BP + lane + q * 32] * sA4[lane + q * 32];
            #pragma unroll
            for (int off = 16; off; off >>= 1) s += __shfl_xor_sync(0xffffffffu, s, off);
            if (lane == 0) sAI[r] = 1.5f * s;
        }
        #pragma unroll
        for (int rr = 0; rr < 8; ++rr) {
            int r = warp * 8 + rr;
            float s = 0.f;
            #pragma unroll
            for (int q = 0; q < 8; ++q) s += sHJ[r * BP + lane + q * 32] * sA4[lane + q * 32];
            #pragma unroll
            for (int off = 16; off; off >>= 1) s += __shfl_xor_sync(0xffffffffu, s, off);
            if (lane == 0) sAJ[r] = 1.5f * s;
        }
    }
    __syncthreads();

    const int ti = t >> 4;
    const int jl = t & 15;
    const u64* u0p = (const u64*)(sUI + ti * BP);
    const u64* u1p = (const u64*)(sUI + (ti + 16) * BP);
    const u64* vp[4];
    #pragma unroll
    for (int q = 0; q < 4; ++q) vp[q] = (const u64*)(sHJ + (jl + q * 16) * BP);
    const u64* ap = (const u64*)sA4;

    u64 acc0[4], acc1[4];
    #pragma unroll
    for (int q = 0; q < 4; ++q) { acc0[q] = 0ull; acc1[q] = 0ull; }

    #pragma unroll 2
    for (int e = 0; e < 128; ++e) {
        u64 ae = ap[e], u0 = u0p[e], u1 = u1p[e];
        #pragma unroll
        for (int q = 0; q < 4; ++q) {
            u64 v = vp[q][e];
            u64 s0, s1;
            ADD2(s0, u0, v); ADD2(s1, u1, v);
            s0 &= ABSMASK;   // |s| packed: 2 LOP3, alu pipe
            s1 &= ABSMASK;
            FMA2(acc0[q], s0, ae, acc0[q]);
            FMA2(acc1[q], s1, ae, acc1[q]);
        }
    }

    // epilogue: final e, tile softmax partials, exp, staged store
    const float ai0 = sAI[ti], ai1 = sAI[ti + 16];
    float v0[4], v1[4];
    #pragma unroll
    for (int q = 0; q < 4; ++q) {
        int jc = jl + q * 16;
        int j  = j0 + jc;
        float lo, hi;
        UNPK(lo, hi, acc0[q]);
        v0[q] = lo + hi + ai0 + sAJ[jc] + ab[(size_t)(i0 + ti) * KF + j];
        UNPK(lo, hi, acc1[q]);
        v1[q] = lo + hi + ai1 + sAJ[jc] + ab[(size_t)(i0 + ti + 16) * KF + j];
    }
    float m0 = fmaxf(fmaxf(v0[0], v0[1]), fmaxf(v0[2], v0[3]));
    float m1 = fmaxf(fmaxf(v1[0], v1[1]), fmaxf(v1[2], v1[3]));
    #pragma unroll
    for (int off = 8; off; off >>= 1) {
        m0 = fmaxf(m0, __shfl_xor_sync(0xffffffffu, m0, off));
        m1 = fmaxf(m1, __shfl_xor_sync(0xffffffffu, m1, off));
    }
    float e0[4], e1[4];
    float s0 = 0.f, s1 = 0.f;
    #pragma unroll
    for (int q = 0; q < 4; ++q) {
        e0[q] = __expf(v0[q] - m0); s0 += e0[q];
        e1[q] = __expf(v1[q] - m1); s1 += e1[q];
    }
    #pragma unroll
    for (int off = 8; off; off >>= 1) {
        s0 += __shfl_xor_sync(0xffffffffu, s0, off);
        s1 += __shfl_xor_sync(0xffffffffu, s1, off);
    }
    if (jl == 0) {
        size_t r0i = (size_t)(b * KF + i0 + ti) * 8 + jt * 2;
        size_t r1i = (size_t)(b * KF + i0 + ti + 16) * 8 + jt * 2;
        g_MS[r0i] = m0; g_MS[r0i + 1] = s0;
        g_MS[r1i] = m1; g_MS[r1i + 1] = s1;
    }

    float* sE = sm;                  // reuse sUI region
    __syncthreads();
    #pragma unroll
    for (int q = 0; q < 4; ++q) {
        int jc = jl + q * 16;
        sE[ti * 66 + jc]        = e0[q];
        sE[(ti + 16) * 66 + jc] = e1[q];
    }
    __syncthreads();
    for (int idx = t; idx < 32 * 64; idx += 256) {
        int r = idx >> 6, c = idx & 63;
        g_ATT[((size_t)b * KF + i0 + r) * KF + j0 + c] = sE[r * 66 + c];
    }
}

// ============================================================================
// kernC: out[b,w,i] = sigmoid( sum_jt corr[i,jt] * sum_j att'[i,j]*x[w,j] )
// corr = exp(m_t - M) / S_total. Staged, coalesced output.
// ============================================================================
#define CP 66
__global__ __launch_bounds__(256)
void kernC(const float* __restrict__ x, float* __restrict__ out)
{
    __shared__ float sAtt[64 * CP];
    __shared__ float sX[32 * CP];
    __shared__ float sOut[32 * CP];
    __shared__ float sCorr[64 * 4];

    const int b  = blockIdx.z;
    const int w0 = blockIdx.y * 32;
    const int i0 = blockIdx.x * 64;
    const int t  = threadIdx.x;
    const int il = t & 15;
    const int tw = t >> 4;

    if (t < 64) {
        const float* p = g_MS + (size_t)(b * KF + i0 + t) * 8;
        float m[4], s[4];
        #pragma unroll
        for (int q = 0; q < 4; ++q) { m[q] = p[q * 2]; s[q] = p[q * 2 + 1]; }
        float M = fmaxf(fmaxf(m[0], m[1]), fmaxf(m[2], m[3]));
        float ex[4];
        float S = 0.f;
        #pragma unroll
        for (int q = 0; q < 4; ++q) { ex[q] = __expf(m[q] - M); S += s[q] * ex[q]; }
        float inv = 1.0f / S;
        #pragma unroll
        for (int q = 0; q < 4; ++q) sCorr[t * 4 + q] = ex[q] * inv;
    }

    u64 acc[4][2];
    #pragma unroll
    for (int qi = 0; qi < 4; ++qi) { acc[qi][0] = 0ull; acc[qi][1] = 0ull; }

    for (int jt = 0; jt < 4; ++jt) {
        __syncthreads();
        const int j0 = jt * 64;
        for (int idx = t; idx < 64 * 16; idx += 256) {
            int r = idx >> 4, c = idx & 15;
            float4 v = *(const float4*)(g_ATT + ((size_t)b * KF + i0 + r) * KF + j0 + c * 4);
            float2* d = (float2*)(sAtt + r * CP + c * 4);
            d[0] = make_float2(v.x, v.y); d[1] = make_float2(v.z, v.w);
        }
        for (int idx = t; idx < 32 * 16; idx += 256) {
            int r = idx >> 4, c = idx & 15;
            float4 v = *(const float4*)(x + ((size_t)b * WIN + w0 + r) * KF + j0 + c * 4);
            float2* d = (float2*)(sX + r * CP + c * 4);
            d[0] = make_float2(v.x, v.y); d[1] = make_float2(v.z, v.w);
        }
        __syncthreads();

        const u64* xp0 = (const u64*)(sX + tw * CP);
        const u64* xp1 = (const u64*)(sX + (tw + 16) * CP);
        const u64* avp[4];
        #pragma unroll
        for (int qi = 0; qi < 4; ++qi) avp[qi] = (const u64*)(sAtt + (il + qi * 16) * CP);

        u64 accP[4][2];
        #pragma unroll
        for (int qi = 0; qi < 4; ++qi) { accP[qi][0] = 0ull; accP[qi][1] = 0ull; }

        #pragma unroll 4
        for (int j = 0; j < 32; ++j) {
            u64 x0 = xp0[j], x1 = xp1[j];
            #pragma unroll
            for (int qi = 0; qi < 4; ++qi) {
                u64 av = avp[qi][j];
                FMA2(accP[qi][0], av, x0, accP[qi][0]);
                FMA2(accP[qi][1], av, x1, accP[qi][1]);
            }
        }
        #pragma unroll
        for (int qi = 0; qi < 4; ++qi) {
            float c = sCorr[(il + qi * 16) * 4 + jt];
            u64 c2; PK(c2, c, c);
            FMA2(acc[qi][0], accP[qi][0], c2, acc[qi][0]);
            FMA2(acc[qi][1], accP[qi][1], c2, acc[qi][1]);
        }
    }

    __syncthreads();
    #pragma unroll
    for (int qi = 0; qi < 4; ++qi) {
        #pragma unroll
        for (int qw = 0; qw < 2; ++qw) {
            float lo, hi; UNPK(lo, hi, acc[qi][qw]);
            float s = lo + hi;
            sOut[(tw + qw * 16) * CP + il + qi * 16] = 1.0f / (1.0f + __expf(-s));
        }
    }
    __syncthreads();
    for (int idx = t; idx < 32 * 64; idx += 256) {
        int r = idx >> 6, c = idx & 63;
        out[((size_t)b * WIN + w0 + r) * KF + i0 + c] = sOut[r * CP + c];
    }
}

// ============================================================================
extern "C" void kernel_launch(void* const* d_in, const int* in_sizes, int n_in,
                              void* d_out, int out_size)
{
    const float* x   = (const float*)d_in[0];
    const float* lw  = (const float*)d_in[1];
    const float* lb  = (const float*)d_in[2];
    const float* a   = (const float*)d_in[3];
    const float* ab  = (const float*)d_in[4];
    float* out = (float*)d_out;

    const int smemA = (64 * XP + 128 * XP) * 4;                      // ~97.5 KB
    const int smemB = (32 * BP + 64 * BP + 256 + 32 + 64) * 4;       // ~98 KB

    cudaFuncSetAttribute(gemmA, cudaFuncAttributeMaxDynamicSharedMemorySize, smemA);
    cudaFuncSetAttribute(kernB, cudaFuncAttributeMaxDynamicSharedMemorySize, smemB);

    gemmA<<<dim3(4, 64), 256, smemA>>>(x, lw, lb);
    kernB<<<dim3(4, 8, NB), 256, smemB>>>(a, ab);
    kernC<<<dim3(4, 4, NB), 256>>>(x, out);
}

// round 7
// speedup vs baseline: 1.4062x; 1.0297x over previous
#include <cuda_runtime.h>

#define NB   16
#define WIN  128
#define KF   256
#define EMB  256

typedef unsigned long long u64;

#define ADD2(d, a, b) asm("add.rn.f32x2 %0, %1, %2;" : "=l"(d) : "l"(a), "l"(b))
#define FMA2(d, a, b, c) asm("fma.rn.f32x2 %0, %1, %2, %3;" : "=l"(d) : "l"(a), "l"(b), "l"(c))
#define UNPK(lo, hi, v) asm("mov.b64 {%0, %1}, %2;" : "=f"(lo), "=f"(hi) : "l"(v))
#define PK(d, lo, hi) asm("mov.b64 %0, {%1, %2};" : "=l"(d) : "f"(lo), "f"(hi))

#define ABSMASK 0x7FFFFFFF7FFFFFFFull

// ---------------- device scratch --------------------------------------------
__device__ float g_UI[NB * KF * EMB];        // hi + lin_b
__device__ float g_HJ[NB * KF * EMB];        // hj
__device__ float g_ATT[NB * KF * KF];        // exp(e - m_tile), per 64-j tile
__device__ float g_MS[NB * KF * 4 * 2];      // per (row, j-tile): max, sumexp

// ============================================================================
// gemmA: fused N=512 GEMM; e'<256 -> UI (+lb), e'>=256 -> HJ.
// 256 threads, tile 64 rows x 128 e', micro 4x8, K stepped 4 floats (LDS.128).
// ============================================================================
#define XP 132   // pitch: mult of 4 (16B rows); 132%32=4
__global__ __launch_bounds__(256, 2)
void gemmA(const float* __restrict__ x, const float* __restrict__ lw,
           const float* __restrict__ lb)
{
    extern __shared__ float sm[];
    float* sXT = sm;                  // [64 k][132]  (w along row)
    float* sW  = sXT + 64 * XP;       // [128 e'][132]

    const int ktile = blockIdx.y;             // 0..63
    const int b  = ktile >> 2;
    const int k0 = (ktile & 3) * 64;
    const int ep = blockIdx.x * 128;          // 0,128,256,384
    const int side = (ep >= 256);
    const int eb   = ep & 255;
    const int woff = side ? WIN : 0;
    const int t  = threadIdx.x;

    const float* xb = x + (size_t)b * WIN * KF + k0;
    for (int idx = t; idx < 128 * 64; idx += 256) {
        int w = idx >> 6, kk = idx & 63;
        sXT[kk * XP + w] = xb[w * KF + kk];
    }
    for (int idx = t; idx < 128 * 128; idx += 256) {
        int ee = idx >> 7, w = idx & 127;
        sW[ee * XP + w] = lw[(eb + ee) * (2 * WIN) + woff + w];
    }
    __syncthreads();

    const int tk = t & 15;   // k rows: tk + ii*16  (ii<4)
    const int te = t >> 4;   // e' cols: te + jj*16 (jj<8)
    const ulonglong2* xq[4];  const ulonglong2* wq[8];
    #pragma unroll
    for (int ii = 0; ii < 4; ++ii) xq[ii] = (const ulonglong2*)(sXT + (tk + ii * 16) * XP);
    #pragma unroll
    for (int jj = 0; jj < 8; ++jj) wq[jj] = (const ulonglong2*)(sW + (te + jj * 16) * XP);

    u64 acc[4][8];
    #pragma unroll
    for (int ii = 0; ii < 4; ++ii)
        #pragma unroll
        for (int jj = 0; jj < 8; ++jj) acc[ii][jj] = 0ull;

    #pragma unroll 2
    for (int s = 0; s < 32; ++s) {           // 4 w per step
        ulonglong2 xv[4];
        #pragma unroll
        for (int ii = 0; ii < 4; ++ii) xv[ii] = xq[ii][s];
        #pragma unroll
        for (int h = 0; h < 2; ++h) {
            ulonglong2 wv[4];
            #pragma unroll
            for (int j4 = 0; j4 < 4; ++j4) wv[j4] = wq[h * 4 + j4][s];
            #pragma unroll
            for (int ii = 0; ii < 4; ++ii)
                #pragma unroll
                for (int j4 = 0; j4 < 4; ++j4) {
                    FMA2(acc[ii][h * 4 + j4], xv[ii].x, wv[j4].x, acc[ii][h * 4 + j4]);
                    FMA2(acc[ii][h * 4 + j4], xv[ii].y, wv[j4].y, acc[ii][h * 4 + j4]);
                }
        }
    }

    float lbv[8];
    #pragma unroll
    for (int jj = 0; jj < 8; ++jj)
        lbv[jj] = side ? 0.f : __ldg(lb + eb + te + jj * 16);

    float* sO = sm;                  // reuse: [64][132]
    __syncthreads();
    #pragma unroll
    for (int ii = 0; ii < 4; ++ii)
        #pragma unroll
        for (int jj = 0; jj < 8; ++jj) {
            float lo, hi; UNPK(lo, hi, acc[ii][jj]);
            sO[(tk + ii * 16) * XP + te + jj * 16] = lo + hi + lbv[jj];
        }
    __syncthreads();
    float* dst = (side ? g_HJ : g_UI) + ((size_t)b * KF + k0) * EMB + eb;
    for (int idx = t; idx < 64 * 64; idx += 256) {
        int r = idx >> 6, c = idx & 63;
        *(float2*)(dst + (size_t)r * EMB + c * 2) = *(float2*)(sO + r * XP + c * 2);
    }
}

// ============================================================================
// kernB: e = 0.6(dot_i+dot_j) + sum 0.4a|u+v| + bias; store exp(e - m_tile);
// partials -> g_MS. leaky(s)=0.6s+0.4|s|. K stepped 4 floats (LDS.128).
// ============================================================================
#define BP 260   // mult of 4; 260%32=4
__global__ __launch_bounds__(256, 2)
void kernB(const float* __restrict__ a, const float* __restrict__ ab)
{
    extern __shared__ float sm[];
    float* sUI = sm;                   // [32][260]
    float* sHJ = sUI + 32 * BP;        // [64][260]
    float* sA4 = sHJ + 64 * BP;        // [256]  0.4*a
    float* sAI = sA4 + 256;            // [32]
    float* sAJ = sAI + 32;             // [64]

    const int b  = blockIdx.z;
    const int i0 = blockIdx.y * 32;
    const int jt = blockIdx.x;
    const int j0 = jt * 64;
    const int t  = threadIdx.x;

    const float4* gu = (const float4*)(g_UI + ((size_t)b * KF + i0) * EMB);
    for (int idx = t; idx < 32 * 64; idx += 256) {
        int r = idx >> 6, c = idx & 63;
        *(float4*)(sUI + r * BP + c * 4) = gu[r * 64 + c];
    }
    const float4* gh = (const float4*)(g_HJ + ((size_t)b * KF + j0) * EMB);
    for (int idx = t; idx < 64 * 64; idx += 256) {
        int r = idx >> 6, c = idx & 63;
        *(float4*)(sHJ + r * BP + c * 4) = gh[r * 64 + c];
    }
    sA4[t] = 0.4f * a[t];
    __syncthreads();

    // row dots: 0.6*dot(row, a) = 1.5*dot(row, 0.4a)
    {
        const int warp = t >> 5, lane = t & 31;
        #pragma unroll
        for (int rr = 0; rr < 4; ++rr) {
            int r = warp * 4 + rr;
            float s = 0.f;
            #pragma unroll
            for (int q = 0; q < 8; ++q) s += sUI[r * BP + lane + q * 32] * sA4[lane + q * 32];
            #pragma unroll
            for (int off = 16; off; off >>= 1) s += __shfl_xor_sync(0xffffffffu, s, off);
            if (lane == 0) sAI[r] = 1.5f * s;
        }
        #pragma unroll
        for (int rr = 0; rr < 8; ++rr) {
            int r = warp * 8 + rr;
            float s = 0.f;
            #pragma unroll
            for (int q = 0; q < 8; ++q) s += sHJ[r * BP + lane + q * 32] * sA4[lane + q * 32];
            #pragma unroll
            for (int off = 16; off; off >>= 1) s += __shfl_xor_sync(0xffffffffu, s, off);
            if (lane == 0) sAJ[r] = 1.5f * s;
        }
    }
    __syncthreads();

    const int ti = t >> 4;
    const int jl = t & 15;
    const ulonglong2* uq0 = (const ulonglong2*)(sUI + ti * BP);
    const ulonglong2* uq1 = (const ulonglong2*)(sUI + (ti + 16) * BP);
    const ulonglong2* vq[4];
    #pragma unroll
    for (int q = 0; q < 4; ++q) vq[q] = (const ulonglong2*)(sHJ + (jl + q * 16) * BP);
    const ulonglong2* aq = (const ulonglong2*)sA4;

    u64 acc0[4], acc1[4];
    #pragma unroll
    for (int q = 0; q < 4; ++q) { acc0[q] = 0ull; acc1[q] = 0ull; }

    #pragma unroll 2
    for (int s = 0; s < 64; ++s) {           // 4 e per step
        ulonglong2 ae = aq[s], u0 = uq0[s], u1 = uq1[s];
        #pragma unroll
        for (int q = 0; q < 4; ++q) {
            ulonglong2 v = vq[q][s];
            u64 s0x, s0y, s1x, s1y;
            ADD2(s0x, u0.x, v.x); ADD2(s0y, u0.y, v.y);
            ADD2(s1x, u1.x, v.x); ADD2(s1y, u1.y, v.y);
            s0x &= ABSMASK; s0y &= ABSMASK;
            s1x &= ABSMASK; s1y &= ABSMASK;
            FMA2(acc0[q], s0x, ae.x, acc0[q]);
            FMA2(acc0[q], s0y, ae.y, acc0[q]);
            FMA2(acc1[q], s1x, ae.x, acc1[q]);
            FMA2(acc1[q], s1y, ae.y, acc1[q]);
        }
    }

    // epilogue: final e, tile softmax partials, exp, staged store
    const float ai0 = sAI[ti], ai1 = sAI[ti + 16];
    float v0[4], v1[4];
    #pragma unroll
    for (int q = 0; q < 4; ++q) {
        int jc = jl + q * 16;
        int j  = j0 + jc;
        float lo, hi;
        UNPK(lo, hi, acc0[q]);
        v0[q] = lo + hi + ai0 + sAJ[jc] + ab[(size_t)(i0 + ti) * KF + j];
        UNPK(lo, hi, acc1[q]);
        v1[q] = lo + hi + ai1 + sAJ[jc] + ab[(size_t)(i0 + ti + 16) * KF + j];
    }
    float m0 = fmaxf(fmaxf(v0[0], v0[1]), fmaxf(v0[2], v0[3]));
    float m1 = fmaxf(fmaxf(v1[0], v1[1]), fmaxf(v1[2], v1[3]));
    #pragma unroll
    for (int off = 8; off; off >>= 1) {
        m0 = fmaxf(m0, __shfl_xor_sync(0xffffffffu, m0, off));
        m1 = fmaxf(m1, __shfl_xor_sync(0xffffffffu, m1, off));
    }
    float e0[4], e1[4];
    float s0 = 0.f, s1 = 0.f;
    #pragma unroll
    for (int q = 0; q < 4; ++q) {
        e0[q] = __expf(v0[q] - m0); s0 += e0[q];
        e1[q] = __expf(v1[q] - m1); s1 += e1[q];
    }
    #pragma unroll
    for (int off = 8; off; off >>= 1) {
        s0 += __shfl_xor_sync(0xffffffffu, s0, off);
        s1 += __shfl_xor_sync(0xffffffffu, s1, off);
    }
    if (jl == 0) {
        size_t r0i = (size_t)(b * KF + i0 + ti) * 8 + jt * 2;
        size_t r1i = (size_t)(b * KF + i0 + ti + 16) * 8 + jt * 2;
        g_MS[r0i] = m0; g_MS[r0i + 1] = s0;
        g_MS[r1i] = m1; g_MS[r1i + 1] = s1;
    }

    float* sE = sm;                  // reuse sUI region
    __syncthreads();
    #pragma unroll
    for (int q = 0; q < 4; ++q) {
        int jc = jl + q * 16;
        sE[ti * 66 + jc]        = e0[q];
        sE[(ti + 16) * 66 + jc] = e1[q];
    }
    __syncthreads();
    for (int idx = t; idx < 32 * 64; idx += 256) {
        int r = idx >> 6, c = idx & 63;
        g_ATT[((size_t)b * KF + i0 + r) * KF + j0 + c] = sE[r * 66 + c];
    }
}

// ============================================================================
// kernC: out[b,w,i] = sigmoid( sum_jt corr[i,jt] * sum_j att'[i,j]*x[w,j] )
// ============================================================================
#define CP 68    // mult of 4; 68%32=4
__global__ __launch_bounds__(256)
void kernC(const float* __restrict__ x, float* __restrict__ out)
{
    __shared__ float sAtt[64 * CP];
    __shared__ float sX[32 * CP];
    __shared__ float sOut[32 * CP];
    __shared__ float sCorr[64 * 4];

    const int b  = blockIdx.z;
    const int w0 = blockIdx.y * 32;
    const int i0 = blockIdx.x * 64;
    const int t  = threadIdx.x;
    const int il = t & 15;
    const int tw = t >> 4;

    if (t < 64) {
        const float* p = g_MS + (size_t)(b * KF + i0 + t) * 8;
        float m[4], s[4];
        #pragma unroll
        for (int q = 0; q < 4; ++q) { m[q] = p[q * 2]; s[q] = p[q * 2 + 1]; }
        float M = fmaxf(fmaxf(m[0], m[1]), fmaxf(m[2], m[3]));
        float ex[4];
        float S = 0.f;
        #pragma unroll
        for (int q = 0; q < 4; ++q) { ex[q] = __expf(m[q] - M); S += s[q] * ex[q]; }
        float inv = 1.0f / S;
        #pragma unroll
        for (int q = 0; q < 4; ++q) sCorr[t * 4 + q] = ex[q] * inv;
    }

    u64 acc[4][2];
    #pragma unroll
    for (int qi = 0; qi < 4; ++qi) { acc[qi][0] = 0ull; acc[qi][1] = 0ull; }

    for (int jt = 0; jt < 4; ++jt) {
        __syncthreads();
        const int j0 = jt * 64;
        for (int idx = t; idx < 64 * 16; idx += 256) {
            int r = idx >> 4, c = idx & 15;
            *(float4*)(sAtt + r * CP + c * 4) =
                *(const float4*)(g_ATT + ((size_t)b * KF + i0 + r) * KF + j0 + c * 4);
        }
        for (int idx = t; idx < 32 * 16; idx += 256) {
            int r = idx >> 4, c = idx & 15;
            *(float4*)(sX + r * CP + c * 4) =
                *(const float4*)(x + ((size_t)b * WIN + w0 + r) * KF + j0 + c * 4);
        }
        __syncthreads();

        const ulonglong2* xq0 = (const ulonglong2*)(sX + tw * CP);
        const ulonglong2* xq1 = (const ulonglong2*)(sX + (tw + 16) * CP);
        const ulonglong2* aq[4];
        #pragma unroll
        for (int qi = 0; qi < 4; ++qi) aq[qi] = (const ulonglong2*)(sAtt + (il + qi * 16) * CP);

        u64 accP[4][2];
        #pragma unroll
        for (int qi = 0; qi < 4; ++qi) { accP[qi][0] = 0ull; accP[qi][1] = 0ull; }

        #pragma unroll 4
        for (int s = 0; s < 16; ++s) {       // 4 j per step
            ulonglong2 x0 = xq0[s], x1 = xq1[s];
            #pragma unroll
            for (int qi = 0; qi < 4; ++qi) {
                ulonglong2 av = aq[qi][s];
                FMA2(accP[qi][0], av.x, x0.x, accP[qi][0]);
                FMA2(accP[qi][0], av.y, x0.y, accP[qi][0]);
                FMA2(accP[qi][1], av.x, x1.x, accP[qi][1]);
                FMA2(accP[qi][1], av.y, x1.y, accP[qi][1]);
            }
        }
        #pragma unroll
        for (int qi = 0; qi < 4; ++qi) {
            float c = sCorr[(il + qi * 16) * 4 + jt];
            u64 c2; PK(c2, c, c);
            FMA2(acc[qi][0], accP[qi][0], c2, acc[qi][0]);
            FMA2(acc[qi][1], accP[qi][1], c2, acc[qi][1]);
        }
    }

    __syncthreads();
    #pragma unroll
    for (int qi = 0; qi < 4; ++qi) {
        #pragma unroll
        for (int qw = 0; qw < 2; ++qw) {
            float lo, hi; UNPK(lo, hi, acc[qi][qw]);
            float s = lo + hi;
            sOut[(tw + qw * 16) * CP + il + qi * 16] = 1.0f / (1.0f + __expf(-s));
        }
    }
    __syncthreads();
    for (int idx = t; idx < 32 * 64; idx += 256) {
        int r = idx >> 6, c = idx & 63;
        out[((size_t)b * WIN + w0 + r) * KF + i0 + c] = sOut[r * CP + c];
    }
}

// ============================================================================
extern "C" void kernel_launch(void* const* d_in, const int* in_sizes, int n_in,
                              void* d_out, int out_size)
{
    const float* x   = (const float*)d_in[0];
    const float* lw  = (const float*)d_in[1];
    const float* lb  = (const float*)d_in[2];
    const float* a   = (const float*)d_in[3];
    const float* ab  = (const float*)d_in[4];
    float* out = (float*)d_out;

    const int smemA = (64 * XP + 128 * XP) * 4;                      // ~99 KB
    const int smemB = (32 * BP + 64 * BP + 256 + 32 + 64) * 4;       // ~99 KB

    cudaFuncSetAttribute(gemmA, cudaFuncAttributeMaxDynamicSharedMemorySize, smemA);
    cudaFuncSetAttribute(kernB, cudaFuncAttributeMaxDynamicSharedMemorySize, smemB);

    gemmA<<<dim3(4, 64), 256, smemA>>>(x, lw, lb);
    kernB<<<dim3(4, 8, NB), 256, smemB>>>(a, ab);
    kernC<<<dim3(4, 4, NB), 256>>>(x, out);
}